// round 1
// baseline (speedup 1.0000x reference)
#include <cuda_runtime.h>
#include <math.h>

#define BB   2
#define SEQ  2048
#define DM   2048
#define NH   16
#define DK   128
#define DVV  85
#define HV   1360      // DVV * NH
#define NV   2720      // HV * 2
#define MT   (BB*SEQ)  // 4096

// ---------------- scratch (static device globals; no allocation) ----------------
__device__ float g_tq[(size_t)MT*DM];   // qp  [4096][2048]
__device__ float g_tk[(size_t)MT*DM];   // kp
__device__ float g_tv[(size_t)MT*NV];   // vp  [4096][2720]
__device__ float g_qr[(size_t)MT*DM];   // roped q  [bh][s][128]
__device__ float g_kr[(size_t)MT*DM];   // roped k
__device__ float g_vr[(size_t)MT*HV];   // gated v  [bh][s][85]
__device__ float g_ob[(size_t)MT*HV];   // attn out [b][s][1360]

// ---------------- generic fp32 GEMM: C[M,N] = A[M,K] @ W[K,N] + bias ----------------
// BM=BN=128, BK=16, 256 threads, 8x8 per thread. M multiple of 128, K multiple of 16.
__global__ __launch_bounds__(256) void gemm_bias(
    const float* __restrict__ A, const float* __restrict__ W,
    const float* __restrict__ bias, float* __restrict__ C, int N, int K)
{
    __shared__ float As[16][128];
    __shared__ float Ws[16][128];
    const int m0 = blockIdx.y * 128;
    const int n0 = blockIdx.x * 128;
    const int tid = threadIdx.x;
    const int tm = tid >> 4, tn = tid & 15;

    float acc[8][8];
    #pragma unroll
    for (int i = 0; i < 8; i++)
        #pragma unroll
        for (int j = 0; j < 8; j++) acc[i][j] = 0.f;

    for (int k0 = 0; k0 < K; k0 += 16) {
        #pragma unroll
        for (int l = 0; l < 2; l++) {
            int lin = tid + l * 256;            // 0..511
            // A tile: 128 rows x 16 k  (512 float4)
            int row = lin >> 2, cc = (lin & 3) * 4;
            float4 av = *(const float4*)&A[(size_t)(m0 + row) * K + k0 + cc];
            As[cc + 0][row] = av.x; As[cc + 1][row] = av.y;
            As[cc + 2][row] = av.z; As[cc + 3][row] = av.w;
            // W tile: 16 k x 128 cols (512 float4), guard N
            int kk = lin >> 5, c4 = (lin & 31) * 4;
            int col = n0 + c4;
            float4 wv = make_float4(0.f, 0.f, 0.f, 0.f);
            if (col < N) wv = *(const float4*)&W[(size_t)(k0 + kk) * N + col];
            *(float4*)&Ws[kk][c4] = wv;
        }
        __syncthreads();
        #pragma unroll
        for (int kk = 0; kk < 16; kk++) {
            float a[8], w[8];
            *(float4*)&a[0] = *(float4*)&As[kk][tm * 8];
            *(float4*)&a[4] = *(float4*)&As[kk][tm * 8 + 4];
            *(float4*)&w[0] = *(float4*)&Ws[kk][tn * 8];
            *(float4*)&w[4] = *(float4*)&Ws[kk][tn * 8 + 4];
            #pragma unroll
            for (int i = 0; i < 8; i++)
                #pragma unroll
                for (int j = 0; j < 8; j++) acc[i][j] += a[i] * w[j];
        }
        __syncthreads();
    }
    #pragma unroll
    for (int i = 0; i < 8; i++) {
        int row = m0 + tm * 8 + i;
        #pragma unroll
        for (int j = 0; j < 8; j++) {
            int col = n0 + tn * 8 + j;
            if (col < N) C[(size_t)row * N + col] = acc[i][j] + bias[col];
        }
    }
}

// ---------------- RoPE + transpose:  [b,s,h*128] -> [bh,s,128] ----------------
__global__ void rope_tr(const float* __restrict__ in, float* __restrict__ out)
{
    int g = blockIdx.x * 256 + threadIdx.x;        // BB*SEQ*NH*64 = 2^22
    int j = g & 63;
    int h = (g >> 6) & 15;
    int s = (g >> 10) & (SEQ - 1);
    int b = g >> 21;
    float inv = 1.0f / powf(10000.0f, (float)j * (1.0f / 64.0f));
    float ang = (float)s * inv;
    float c, sn;
    sincosf(ang, &sn, &c);
    const float* ip = in + ((size_t)(b * SEQ + s)) * DM + h * DK;
    float x1 = ip[j], x2 = ip[j + 64];
    float* op = out + ((size_t)((b * NH + h) * SEQ + s)) * DK;
    op[j]      = x1 * c - x2 * sn;
    op[j + 64] = x2 * c + x1 * sn;
}

// ---------------- SiLU-GLU + head split:  vp[4096][2720] -> [bh][s][85] ----------------
__global__ void glu_tr(const float* __restrict__ in, float* __restrict__ out)
{
    int g = blockIdx.x * 256 + threadIdx.x;        // MT*HV
    if (g >= MT * HV) return;
    int col = g % HV;
    int m   = g / HV;
    int b = m >> 11, s = m & (SEQ - 1);
    float a = in[(size_t)m * NV + col];
    float x = in[(size_t)m * NV + HV + col];
    float val = a * x / (1.0f + __expf(-x));
    int h = col / DVV, dv = col - h * DVV;
    out[((size_t)((b * NH + h) * SEQ + s)) * DVV + dv] = val;
}

// ---------------- flash attention (fp32, causal) ----------------
// grid: (S/64, B*H). 256 threads. 64-query x 64-key tiles.
#define TQ 64
#define TK 64
#define QSTR 65          // qT/kT row stride (transposed [d][r])
#define VSTR 96          // v tile row stride (85 cols, zero padded)
#define PSTR 68          // probability tile row stride

#define ATT_SMEM ((128*QSTR + 128*QSTR + TK*VSTR + TQ*PSTR + 3*TQ) * 4)

__global__ __launch_bounds__(256) void attn_fwd(
    const float* __restrict__ Q, const float* __restrict__ Kb,
    const float* __restrict__ V, float* __restrict__ O)
{
    extern __shared__ float sm[];
    float* qT  = sm;                       // [128][65]
    float* kT  = qT + 128 * QSTR;          // [128][65]
    float* vs  = kT + 128 * QSTR;          // [64][96]
    float* Ps  = vs + TK * VSTR;           // [64][68]
    float* m_s = Ps + TQ * PSTR;
    float* l_s = m_s + TQ;
    float* al_s = l_s + TQ;

    const int qt = blockIdx.x, bh = blockIdx.y;
    const int tid = threadIdx.x;
    const int ty = tid >> 4, tx = tid & 15;
    const float scale = 0.08838834764831845f;   // 1/sqrt(128)

    const float* Qb = Q + ((size_t)bh * SEQ + qt * TQ) * DK;
    for (int i = tid; i < TQ * DK; i += 256) {
        int d = i & 127, r = i >> 7;
        qT[d * QSTR + r] = Qb[(size_t)r * DK + d];
    }
    if (tid < TQ) { m_s[tid] = -1e30f; l_s[tid] = 0.f; }
    float acc[4][6];
    #pragma unroll
    for (int i = 0; i < 4; i++)
        #pragma unroll
        for (int j = 0; j < 6; j++) acc[i][j] = 0.f;
    __syncthreads();

    for (int kt = 0; kt <= qt; kt++) {
        const float* Kbp = Kb + ((size_t)bh * SEQ + kt * TK) * DK;
        for (int i = tid; i < TK * DK; i += 256) {
            int d = i & 127, r = i >> 7;
            kT[d * QSTR + r] = Kbp[(size_t)r * DK + d];
        }
        const float* Vb = V + ((size_t)bh * SEQ + kt * TK) * DVV;
        for (int i = tid; i < TK * VSTR; i += 256) {
            int r = i / VSTR, c = i - r * VSTR;
            vs[i] = (c < DVV) ? Vb[(size_t)r * DVV + c] : 0.f;
        }
        __syncthreads();

        // scores: 64x64, 16x16 threads x (4x4)
        float sc[4][4];
        #pragma unroll
        for (int i = 0; i < 4; i++)
            #pragma unroll
            for (int j = 0; j < 4; j++) sc[i][j] = 0.f;
        #pragma unroll 4
        for (int kk = 0; kk < DK; kk++) {
            float a[4], b[4];
            #pragma unroll
            for (int i = 0; i < 4; i++) a[i] = qT[kk * QSTR + ty * 4 + i];
            #pragma unroll
            for (int j = 0; j < 4; j++) b[j] = kT[kk * QSTR + tx * 4 + j];
            #pragma unroll
            for (int i = 0; i < 4; i++)
                #pragma unroll
                for (int j = 0; j < 4; j++) sc[i][j] += a[i] * b[j];
        }
        int qg0 = qt * TQ + ty * 4;
        int kg0 = kt * TK + tx * 4;
        #pragma unroll
        for (int i = 0; i < 4; i++)
            #pragma unroll
            for (int j = 0; j < 4; j++) {
                float v = sc[i][j] * scale;
                if (kg0 + j > qg0 + i) v = -1e30f;
                Ps[(ty * 4 + i) * PSTR + tx * 4 + j] = v;
            }
        __syncthreads();

        // online softmax: 4 threads per row
        {
            int r = tid >> 2, q4 = tid & 3;
            int base = r * PSTR + q4 * 16;
            float mloc = -1e30f;
            #pragma unroll
            for (int j = 0; j < 16; j++) mloc = fmaxf(mloc, Ps[base + j]);
            mloc = fmaxf(mloc, __shfl_xor_sync(0xffffffffu, mloc, 1));
            mloc = fmaxf(mloc, __shfl_xor_sync(0xffffffffu, mloc, 2));
            float mold = m_s[r];
            float mnew = fmaxf(mold, mloc);
            float sum = 0.f;
            #pragma unroll
            for (int j = 0; j < 16; j++) {
                float p = __expf(Ps[base + j] - mnew);
                Ps[base + j] = p;
                sum += p;
            }
            sum += __shfl_xor_sync(0xffffffffu, sum, 1);
            sum += __shfl_xor_sync(0xffffffffu, sum, 2);
            if (q4 == 0) {
                float alpha = __expf(mold - mnew);
                l_s[r] = l_s[r] * alpha + sum;
                m_s[r] = mnew;
                al_s[r] = alpha;
            }
        }
        __syncthreads();

        // O accumulate: thread covers rows 4*ty..+3, cols tx+16*j (j<6)
        #pragma unroll
        for (int i = 0; i < 4; i++) {
            float alpha = al_s[ty * 4 + i];
            #pragma unroll
            for (int j = 0; j < 6; j++) acc[i][j] *= alpha;
        }
        #pragma unroll 2
        for (int kk = 0; kk < TK; kk++) {
            float vv[6];
            #pragma unroll
            for (int j = 0; j < 6; j++) vv[j] = vs[kk * VSTR + tx + 16 * j];
            #pragma unroll
            for (int i = 0; i < 4; i++) {
                float p = Ps[(ty * 4 + i) * PSTR + kk];
                #pragma unroll
                for (int j = 0; j < 6; j++) acc[i][j] += p * vv[j];
            }
        }
        __syncthreads();
    }

    const int b = bh >> 4, h = bh & 15;
    #pragma unroll
    for (int i = 0; i < 4; i++) {
        int qg = qt * TQ + ty * 4 + i;
        float inv_l = 1.0f / l_s[ty * 4 + i];
        #pragma unroll
        for (int j = 0; j < 6; j++) {
            int c = tx + 16 * j;
            if (c < DVV)
                O[((size_t)(b * SEQ + qg)) * HV + h * DVV + c] = acc[i][j] * inv_l;
        }
    }
}

// ---------------- launch ----------------
extern "C" void kernel_launch(void* const* d_in, const int* in_sizes, int n_in,
                              void* d_out, int out_size)
{
    const float* q  = (const float*)d_in[0];
    const float* k  = (const float*)d_in[1];
    const float* v  = (const float*)d_in[2];
    // d_in[3] = mask (causal, reconstructed analytically)
    const float* Wq = (const float*)d_in[4];
    const float* bq = (const float*)d_in[5];
    const float* Wk = (const float*)d_in[6];
    const float* bk = (const float*)d_in[7];
    const float* Wv = (const float*)d_in[8];
    const float* bv = (const float*)d_in[9];
    const float* Wo = (const float*)d_in[10];
    const float* bo = (const float*)d_in[11];
    float* out = (float*)d_out;

    float *tq, *tk, *tv, *qr, *kr, *vr, *ob;
    cudaGetSymbolAddress((void**)&tq, g_tq);
    cudaGetSymbolAddress((void**)&tk, g_tk);
    cudaGetSymbolAddress((void**)&tv, g_tv);
    cudaGetSymbolAddress((void**)&qr, g_qr);
    cudaGetSymbolAddress((void**)&kr, g_kr);
    cudaGetSymbolAddress((void**)&vr, g_vr);
    cudaGetSymbolAddress((void**)&ob, g_ob);

    // projections
    gemm_bias<<<dim3(16, 32), 256>>>(q, Wq, bq, tq, DM, DM);
    gemm_bias<<<dim3(16, 32), 256>>>(k, Wk, bk, tk, DM, DM);
    gemm_bias<<<dim3(22, 32), 256>>>(v, Wv, bv, tv, NV, DM);

    // rope + transpose (q, k), glu + transpose (v)
    const int nrope = BB * SEQ * NH * 64;
    rope_tr<<<nrope / 256, 256>>>(tq, qr);
    rope_tr<<<nrope / 256, 256>>>(tk, kr);
    const int nglu = MT * HV;
    glu_tr<<<(nglu + 255) / 256, 256>>>(tv, vr);

    // attention
    cudaFuncSetAttribute(attn_fwd, cudaFuncAttributeMaxDynamicSharedMemorySize, ATT_SMEM);
    attn_fwd<<<dim3(SEQ / TQ, BB * NH), 256, ATT_SMEM>>>(qr, kr, vr, ob);

    // output projection
    gemm_bias<<<dim3(16, 32), 256>>>(ob, Wo, bo, out, DM, HV);
}

// round 4
// speedup vs baseline: 2.1348x; 2.1348x over previous
#include <cuda_runtime.h>
#include <math.h>
#include <stdint.h>

#define BB   2
#define SEQ  2048
#define DM   2048
#define NH   16
#define DKH  128
#define DVV  85
#define DVP  88        // padded per-head value dim
#define HV   1360      // DVV * NH
#define HVP  1408      // DVP * NH (padded, multiple of 32)
#define NV   2720      // HV * 2
#define MT   (BB*SEQ)  // 4096

// ---------------- scratch (static device globals) ----------------
__device__ float g_tq[(size_t)MT*DM];
__device__ float g_tk[(size_t)MT*DM];
__device__ float g_tv[(size_t)MT*NV];
__device__ float g_qr[(size_t)MT*DM];
__device__ float g_kr[(size_t)MT*DM];
__device__ float g_vr[(size_t)MT*HV];
__device__ float g_ob[(size_t)MT*HVP];     // attn out, padded, tf32-rounded
__device__ float g_qc[(size_t)MT*DM];      // tf32-rounded activations
__device__ float g_kc[(size_t)MT*DM];
__device__ float g_vc[(size_t)MT*DM];
__device__ float g_wq[(size_t)DM*DM];      // Wq^T [N][K], tf32-rounded
__device__ float g_wk[(size_t)DM*DM];
__device__ float g_wv[(size_t)NV*DM];
__device__ float g_wo[(size_t)DM*HVP];     // Wo^T padded [2048][1408]

// ---------------- helpers ----------------
__device__ __forceinline__ float to_tf32(float x) {
    uint32_t u;
    asm("cvt.rna.tf32.f32 %0, %1;" : "=r"(u) : "f"(x));
    return __uint_as_float(u);
}
__device__ __forceinline__ uint32_t smem_u32(const void* p) {
    uint32_t a;
    asm("{ .reg .u64 t; cvta.to.shared.u64 t, %1; cvt.u32.u64 %0, t; }" : "=r"(a) : "l"(p));
    return a;
}
__device__ __forceinline__ void cp16(uint32_t dst, const void* src, int valid_bytes) {
    asm volatile("cp.async.cg.shared.global [%0], [%1], 16, %2;"
                 :: "r"(dst), "l"(src), "r"(valid_bytes) : "memory");
}
#define CP_COMMIT() asm volatile("cp.async.commit_group;" ::: "memory")
#define CP_WAIT1()  asm volatile("cp.async.wait_group 1;" ::: "memory")

__device__ __forceinline__ void mma8(float* c, const uint32_t* a, const uint32_t* b) {
    asm volatile(
        "mma.sync.aligned.m16n8k8.row.col.f32.tf32.tf32.f32 "
        "{%0,%1,%2,%3}, {%4,%5,%6,%7}, {%8,%9}, {%0,%1,%2,%3};"
        : "+f"(c[0]), "+f"(c[1]), "+f"(c[2]), "+f"(c[3])
        : "r"(a[0]), "r"(a[1]), "r"(a[2]), "r"(a[3]), "r"(b[0]), "r"(b[1]));
}

// ---------------- tf32 warp-MMA GEMM ----------------
// C[M,N] = A[M,K] @ Wt[N,K]^T + bias.  A,Wt pre-rounded to tf32.
// CTA tile 128x128, BK=32, 8 warps (2x4), warp tile 64x32, 3-stage cp.async.
#define BM 128
#define BN 128
#define BK 32
#define AST 36                               // padded row stride (floats)
#define STAGE_F ((BM + BN) * AST)            // 9216 floats / stage
#define GSMEM   (3 * STAGE_F * 4)            // 110592 bytes

__device__ __forceinline__ void g_load_stage(
    const float* __restrict__ A, const float* __restrict__ Wt,
    int N, int K, int m0, int n0, int k0, float* st, int tid)
{
    #pragma unroll
    for (int i = 0; i < 8; i++) {
        int ch = tid + i * 256;              // 0..2047
        int row = ch >> 3, c = ch & 7;
        uint32_t dst = smem_u32(st + row * AST + c * 4);
        if (row < BM) {
            cp16(dst, A + (size_t)(m0 + row) * K + k0 + c * 4, 16);
        } else {
            int n = n0 + row - BM;
            int nc = n < N ? n : N - 1;
            cp16(dst, Wt + (size_t)nc * K + k0 + c * 4, n < N ? 16 : 0);
        }
    }
}

__global__ __launch_bounds__(256, 2) void gemm_tc(
    const float* __restrict__ A, const float* __restrict__ Wt,
    const float* __restrict__ bias, float* __restrict__ C, int N, int K)
{
    extern __shared__ float smf[];
    const int tid = threadIdx.x;
    const int wid = tid >> 5, lane = tid & 31;
    const int m0 = blockIdx.y * BM, n0 = blockIdx.x * BN;
    const int warp_m = wid & 1, warp_n = wid >> 1;   // 2 x 4
    const int r = lane >> 2, tig = lane & 3;

    float acc[4][4][4];
    #pragma unroll
    for (int mt = 0; mt < 4; mt++)
        #pragma unroll
        for (int nt = 0; nt < 4; nt++)
            #pragma unroll
            for (int j = 0; j < 4; j++) acc[mt][nt][j] = 0.f;

    const int NIT = K / BK;
    g_load_stage(A, Wt, N, K, m0, n0, 0, smf, tid);            CP_COMMIT();
    g_load_stage(A, Wt, N, K, m0, n0, BK, smf + STAGE_F, tid); CP_COMMIT();

    for (int it = 0; it < NIT; it++) {
        float* st = smf + (it % 3) * STAGE_F;
        CP_WAIT1();
        __syncthreads();
        if (it + 2 < NIT)
            g_load_stage(A, Wt, N, K, m0, n0, (it + 2) * BK,
                         smf + ((it + 2) % 3) * STAGE_F, tid);
        CP_COMMIT();

        const float* As = st;
        const float* Bs = st + BM * AST;
        #pragma unroll
        for (int step = 0; step < 4; step++) {
            const int kb = step * 8;
            uint32_t afr[4][4], bfr[4][2];
            #pragma unroll
            for (int mt = 0; mt < 4; mt++) {
                const float* ap = As + (warp_m * 64 + mt * 16 + r) * AST + kb;
                afr[mt][0] = __float_as_uint(ap[tig]);
                afr[mt][1] = __float_as_uint(ap[8 * AST + tig]);
                afr[mt][2] = __float_as_uint(ap[tig + 4]);
                afr[mt][3] = __float_as_uint(ap[8 * AST + tig + 4]);
            }
            #pragma unroll
            for (int nt = 0; nt < 4; nt++) {
                const float* bp = Bs + (warp_n * 32 + nt * 8 + r) * AST + kb;
                bfr[nt][0] = __float_as_uint(bp[tig]);
                bfr[nt][1] = __float_as_uint(bp[tig + 4]);
            }
            #pragma unroll
            for (int mt = 0; mt < 4; mt++)
                #pragma unroll
                for (int nt = 0; nt < 4; nt++)
                    mma8(acc[mt][nt], afr[mt], bfr[nt]);
        }
        __syncthreads();
    }

    // epilogue
    #pragma unroll
    for (int mt = 0; mt < 4; mt++) {
        int row = m0 + warp_m * 64 + mt * 16 + r;
        #pragma unroll
        for (int nt = 0; nt < 4; nt++) {
            int col = n0 + warp_n * 32 + nt * 8 + 2 * tig;
            if (col < N) {
                float b0 = bias[col], b1 = bias[col + 1];
                float2 v0 = make_float2(acc[mt][nt][0] + b0, acc[mt][nt][1] + b1);
                float2 v1 = make_float2(acc[mt][nt][2] + b0, acc[mt][nt][3] + b1);
                *(float2*)&C[(size_t)row * N + col] = v0;
                *(float2*)&C[(size_t)(row + 8) * N + col] = v1;
            }
        }
    }
}

// ---------------- tf32 rounding pass (activations) ----------------
__global__ void cvt_tf32_k(const float4* __restrict__ in, float4* __restrict__ out, int n4)
{
    int i = blockIdx.x * 256 + threadIdx.x;
    if (i < n4) {
        float4 v = in[i];
        v.x = to_tf32(v.x); v.y = to_tf32(v.y);
        v.z = to_tf32(v.z); v.w = to_tf32(v.w);
        out[i] = v;
    }
}

// ---------------- weight transposes (with tf32 rounding) ----------------
__global__ void transpose_f(const float* __restrict__ in, float* __restrict__ out, int R, int C)
{
    __shared__ float t[32][33];
    int cb = blockIdx.x * 32, rb = blockIdx.y * 32;
    t[threadIdx.y][threadIdx.x] = in[(size_t)(rb + threadIdx.y) * C + cb + threadIdx.x];
    __syncthreads();
    out[(size_t)(cb + threadIdx.y) * R + rb + threadIdx.x] = to_tf32(t[threadIdx.x][threadIdx.y]);
}

// Wo [1360][2048] -> Wo^T padded [2048][1408]
__global__ void transpose_wo(const float* __restrict__ in, float* __restrict__ out)
{
    __shared__ float t[32][33];
    int mpb = blockIdx.x * 32, nb = blockIdx.y * 32;
    {
        int mp = mpb + threadIdx.y;
        int h = mp / DVP, j = mp - h * DVP;
        float v = 0.f;
        if (j < DVV) v = in[(size_t)(h * DVV + j) * DM + nb + threadIdx.x];
        t[threadIdx.y][threadIdx.x] = v;
    }
    __syncthreads();
    out[(size_t)(nb + threadIdx.y) * HVP + mpb + threadIdx.x] = to_tf32(t[threadIdx.x][threadIdx.y]);
}

// ---------------- RoPE + transpose:  [b,s,h*128] -> [bh,s,128] ----------------
__global__ void rope_tr(const float* __restrict__ in, float* __restrict__ out)
{
    int g = blockIdx.x * 256 + threadIdx.x;
    int j = g & 63;
    int h = (g >> 6) & 15;
    int s = (g >> 10) & (SEQ - 1);
    int b = g >> 21;
    float inv = 1.0f / powf(10000.0f, (float)j * (1.0f / 64.0f));
    float ang = (float)s * inv;
    float c, sn;
    sincosf(ang, &sn, &c);
    const float* ip = in + ((size_t)(b * SEQ + s)) * DM + h * DKH;
    float x1 = ip[j], x2 = ip[j + 64];
    float* op = out + ((size_t)((b * NH + h) * SEQ + s)) * DKH;
    op[j]      = x1 * c - x2 * sn;
    op[j + 64] = x2 * c + x1 * sn;
}

// ---------------- SiLU-GLU + head split ----------------
__global__ void glu_tr(const float* __restrict__ in, float* __restrict__ out)
{
    int g = blockIdx.x * 256 + threadIdx.x;
    if (g >= MT * HV) return;
    int col = g % HV;
    int m   = g / HV;
    int b = m >> 11, s = m & (SEQ - 1);
    float a = in[(size_t)m * NV + col];
    float x = in[(size_t)m * NV + HV + col];
    float val = a * x / (1.0f + __expf(-x));
    int h = col / DVV, dv = col - h * DVV;
    out[((size_t)((b * NH + h) * SEQ + s)) * DVV + dv] = val;
}

// ---------------- flash attention (fp32, causal) ----------------
#define TQ 64
#define TK 64
#define QSTR 65
#define VSTR 96
#define PSTR 68
#define ATT_SMEM ((128*QSTR + 128*QSTR + TK*VSTR + TQ*PSTR + 3*TQ) * 4)

__global__ __launch_bounds__(256) void attn_fwd(
    const float* __restrict__ Q, const float* __restrict__ Kb,
    const float* __restrict__ V, float* __restrict__ O)
{
    extern __shared__ float sm[];
    float* qT  = sm;
    float* kT  = qT + 128 * QSTR;
    float* vs  = kT + 128 * QSTR;
    float* Ps  = vs + TK * VSTR;
    float* m_s = Ps + TQ * PSTR;
    float* l_s = m_s + TQ;
    float* al_s = l_s + TQ;

    const int qt = blockIdx.x, bh = blockIdx.y;
    const int tid = threadIdx.x;
    const int ty = tid >> 4, tx = tid & 15;
    const float scale = 0.08838834764831845f;

    const float* Qb = Q + ((size_t)bh * SEQ + qt * TQ) * DKH;
    for (int i = tid; i < TQ * DKH; i += 256) {
        int d = i & 127, rr = i >> 7;
        qT[d * QSTR + rr] = Qb[(size_t)rr * DKH + d];
    }
    if (tid < TQ) { m_s[tid] = -1e30f; l_s[tid] = 0.f; }
    float acc[4][6];
    #pragma unroll
    for (int i = 0; i < 4; i++)
        #pragma unroll
        for (int j = 0; j < 6; j++) acc[i][j] = 0.f;
    __syncthreads();

    for (int kt = 0; kt <= qt; kt++) {
        const float* Kbp = Kb + ((size_t)bh * SEQ + kt * TK) * DKH;
        for (int i = tid; i < TK * DKH; i += 256) {
            int d = i & 127, rr = i >> 7;
            kT[d * QSTR + rr] = Kbp[(size_t)rr * DKH + d];
        }
        const float* Vb = V + ((size_t)bh * SEQ + kt * TK) * DVV;
        for (int i = tid; i < TK * VSTR; i += 256) {
            int rr = i / VSTR, c = i - rr * VSTR;
            vs[i] = (c < DVV) ? Vb[(size_t)rr * DVV + c] : 0.f;
        }
        __syncthreads();

        float sc[4][4];
        #pragma unroll
        for (int i = 0; i < 4; i++)
            #pragma unroll
            for (int j = 0; j < 4; j++) sc[i][j] = 0.f;
        #pragma unroll 4
        for (int kk = 0; kk < DKH; kk++) {
            float a[4], b[4];
            #pragma unroll
            for (int i = 0; i < 4; i++) a[i] = qT[kk * QSTR + ty * 4 + i];
            #pragma unroll
            for (int j = 0; j < 4; j++) b[j] = kT[kk * QSTR + tx * 4 + j];
            #pragma unroll
            for (int i = 0; i < 4; i++)
                #pragma unroll
                for (int j = 0; j < 4; j++) sc[i][j] += a[i] * b[j];
        }
        int qg0 = qt * TQ + ty * 4;
        int kg0 = kt * TK + tx * 4;
        #pragma unroll
        for (int i = 0; i < 4; i++)
            #pragma unroll
            for (int j = 0; j < 4; j++) {
                float v = sc[i][j] * scale;
                if (kg0 + j > qg0 + i) v = -1e30f;
                Ps[(ty * 4 + i) * PSTR + tx * 4 + j] = v;
            }
        __syncthreads();

        {
            int rr = tid >> 2, q4 = tid & 3;
            int base = rr * PSTR + q4 * 16;
            float mloc = -1e30f;
            #pragma unroll
            for (int j = 0; j < 16; j++) mloc = fmaxf(mloc, Ps[base + j]);
            mloc = fmaxf(mloc, __shfl_xor_sync(0xffffffffu, mloc, 1));
            mloc = fmaxf(mloc, __shfl_xor_sync(0xffffffffu, mloc, 2));
            float mold = m_s[rr];
            float mnew = fmaxf(mold, mloc);
            float sum = 0.f;
            #pragma unroll
            for (int j = 0; j < 16; j++) {
                float p = __expf(Ps[base + j] - mnew);
                Ps[base + j] = p;
                sum += p;
            }
            sum += __shfl_xor_sync(0xffffffffu, sum, 1);
            sum += __shfl_xor_sync(0xffffffffu, sum, 2);
            if (q4 == 0) {
                float alpha = __expf(mold - mnew);
                l_s[rr] = l_s[rr] * alpha + sum;
                m_s[rr] = mnew;
                al_s[rr] = alpha;
            }
        }
        __syncthreads();

        #pragma unroll
        for (int i = 0; i < 4; i++) {
            float alpha = al_s[ty * 4 + i];
            #pragma unroll
            for (int j = 0; j < 6; j++) acc[i][j] *= alpha;
        }
        #pragma unroll 2
        for (int kk = 0; kk < TK; kk++) {
            float vv[6];
            #pragma unroll
            for (int j = 0; j < 6; j++) vv[j] = vs[kk * VSTR + tx + 16 * j];
            #pragma unroll
            for (int i = 0; i < 4; i++) {
                float p = Ps[(ty * 4 + i) * PSTR + kk];
                #pragma unroll
                for (int j = 0; j < 6; j++) acc[i][j] += p * vv[j];
            }
        }
        __syncthreads();
    }

    const int b = bh >> 4, h = bh & 15;
    #pragma unroll
    for (int i = 0; i < 4; i++) {
        int qg = qt * TQ + ty * 4 + i;
        float inv_l = 1.0f / l_s[ty * 4 + i];
        #pragma unroll
        for (int j = 0; j < 6; j++) {
            int c = tx + 16 * j;
            if (c < DVP)
                O[((size_t)(b * SEQ + qg)) * HVP + h * DVP + c] =
                    (c < DVV) ? to_tf32(acc[i][j] * inv_l) : 0.f;
        }
    }
}

// ---------------- launch ----------------
extern "C" void kernel_launch(void* const* d_in, const int* in_sizes, int n_in,
                              void* d_out, int out_size)
{
    const float* q  = (const float*)d_in[0];
    const float* k  = (const float*)d_in[1];
    const float* v  = (const float*)d_in[2];
    const float* Wq = (const float*)d_in[4];
    const float* bq = (const float*)d_in[5];
    const float* Wk = (const float*)d_in[6];
    const float* bk = (const float*)d_in[7];
    const float* Wv = (const float*)d_in[8];
    const float* bv = (const float*)d_in[9];
    const float* Wo = (const float*)d_in[10];
    const float* bo = (const float*)d_in[11];
    float* out = (float*)d_out;

    float *tq, *tk, *tv, *qr, *kr, *vr, *ob, *qc, *kc, *vc, *wq, *wk, *wv, *wo;
    cudaGetSymbolAddress((void**)&tq, g_tq);
    cudaGetSymbolAddress((void**)&tk, g_tk);
    cudaGetSymbolAddress((void**)&tv, g_tv);
    cudaGetSymbolAddress((void**)&qr, g_qr);
    cudaGetSymbolAddress((void**)&kr, g_kr);
    cudaGetSymbolAddress((void**)&vr, g_vr);
    cudaGetSymbolAddress((void**)&ob, g_ob);
    cudaGetSymbolAddress((void**)&qc, g_qc);
    cudaGetSymbolAddress((void**)&kc, g_kc);
    cudaGetSymbolAddress((void**)&vc, g_vc);
    cudaGetSymbolAddress((void**)&wq, g_wq);
    cudaGetSymbolAddress((void**)&wk, g_wk);
    cudaGetSymbolAddress((void**)&wv, g_wv);
    cudaGetSymbolAddress((void**)&wo, g_wo);

    cudaFuncSetAttribute(gemm_tc, cudaFuncAttributeMaxDynamicSharedMemorySize, GSMEM);
    cudaFuncSetAttribute(attn_fwd, cudaFuncAttributeMaxDynamicSharedMemorySize, ATT_SMEM);

    // weight transposes (K-major, tf32-rounded)
    transpose_f<<<dim3(DM / 32, DM / 32), dim3(32, 32)>>>(Wq, wq, DM, DM);
    transpose_f<<<dim3(DM / 32, DM / 32), dim3(32, 32)>>>(Wk, wk, DM, DM);
    transpose_f<<<dim3(NV / 32, DM / 32), dim3(32, 32)>>>(Wv, wv, DM, NV);
    transpose_wo<<<dim3(HVP / 32, DM / 32), dim3(32, 32)>>>(Wo, wo);

    // tf32-round activations
    const int n4 = MT * DM / 4;
    cvt_tf32_k<<<(n4 + 255) / 256, 256>>>((const float4*)q, (float4*)qc, n4);
    cvt_tf32_k<<<(n4 + 255) / 256, 256>>>((const float4*)k, (float4*)kc, n4);
    cvt_tf32_k<<<(n4 + 255) / 256, 256>>>((const float4*)v, (float4*)vc, n4);

    // projections (warp-MMA tf32)
    gemm_tc<<<dim3(16, 32), 256, GSMEM>>>(qc, wq, bq, tq, DM, DM);
    gemm_tc<<<dim3(16, 32), 256, GSMEM>>>(kc, wk, bk, tk, DM, DM);
    gemm_tc<<<dim3(22, 32), 256, GSMEM>>>(vc, wv, bv, tv, NV, DM);

    // rope + transpose (q, k), glu + transpose (v)
    const int nrope = BB * SEQ * NH * 64;
    rope_tr<<<nrope / 256, 256>>>(tq, qr);
    rope_tr<<<nrope / 256, 256>>>(tk, kr);
    const int nglu = MT * HV;
    glu_tr<<<(nglu + 255) / 256, 256>>>(tv, vr);

    // attention (fp32, writes padded tf32-rounded layout)
    attn_fwd<<<dim3(SEQ / TQ, BB * NH), 256, ATT_SMEM>>>(qr, kr, vr, ob);

    // output projection (K = 1408 padded)
    gemm_tc<<<dim3(16, 32), 256, GSMEM>>>(ob, wo, bo, out, DM, HVP);
}